// round 9
// baseline (speedup 1.0000x reference)
#include <cuda_runtime.h>
#include <cstdint>
#include <cstddef>

// ---------------------------------------------------------------------------
// FullAttentionEstimator: B=2, Tq=Tk=512, Q_DIM=K_DIM=1024, HID=128
//
// Factorization:
//   q = Q@Wq, k = K@Wk                       (per-row, precomputed)
//   x = [q, k, q*k]  (384)
//   LN(x)@W = r*(x@(g.W)) - r*mu*(g@W) + (b@W + bias)
//   x@(g.W) = q@W1 + k@W2 + p@W3,  p = q*k  (per pair)
// Cross term p@W3 is an fp32 GEMM (FFMA2, split-K x2, 512 threads);
// per-tile operands double-buffered; epilogue fuses LN recombine + erf-gelu
// + Wo dot. q/k tile rows padded to 132 floats (bank-conflict-free P build).
// ---------------------------------------------------------------------------

#define B_    2
#define HID_  128
#define EPSV  1e-5f

typedef unsigned long long ull;

// -------------------- device scratch (no allocations allowed) --------------
__device__ float dW1[128 * 256];     // g-scaled Wu|Wv rows 0..127   [c][n]
__device__ float dW2[128 * 256];     // rows 128..255
__device__ float dWc[128 * 256];     // rows 256..383 (cross weights)
__device__ float dG[256];            // sum_c g_c W[c][n]
__device__ float dB0[256];           // sum_c b_c W[c][n] + bias[n]
__device__ float d_q[1024 * 128];    // projected q rows (B*Tq)
__device__ float d_k[1024 * 128];
__device__ float dAu[1024 * 256];    // q@W1 (u|v)
__device__ float dBk[1024 * 256];    // k@W2 (u|v)
__device__ float dsq[1024], dsq2[1024], dsk[1024], dsk2[1024];

// -------------------- packed f32x2 helpers ---------------------------------
__device__ __forceinline__ ull pack2(float x) {
    ull r;
    asm("mov.b64 %0, {%1, %1};" : "=l"(r) : "r"(__float_as_uint(x)));
    return r;
}
__device__ __forceinline__ void unpack2(ull v, float& lo, float& hi) {
    asm("mov.b64 {%0, %1}, %2;" : "=f"(lo), "=f"(hi) : "l"(v));
}
__device__ __forceinline__ ull add2(ull a, ull b) {
    ull r;
    asm("add.rn.f32x2 %0, %1, %2;" : "=l"(r) : "l"(a), "l"(b));
    return r;
}
__device__ __forceinline__ ull fma2n(ull a, ull b, ull c) {
    ull r;
    asm("fma.rn.f32x2 %0, %1, %2, %3;" : "=l"(r) : "l"(a), "l"(b), "l"(c));
    return r;
}
#define FMA2(acc, a, b) \
    asm("fma.rn.f32x2 %0, %1, %2, %0;" : "+l"(acc) : "l"(a), "l"(b))

__device__ __forceinline__ float gelu_ex(float v) {
    // exact gelu: v * Phi(v); erff is branch-free & 2-ulp accurate
    return v * (0.5f + 0.5f * erff(v * 0.70710678118654752f));
}

// ===========================================================================
// Kernel 1: derived weights. 256 blocks (one per output col n), 384 threads.
// ===========================================================================
__global__ void deriv_kernel(const float* __restrict__ ln_g, const float* __restrict__ ln_b,
                             const float* __restrict__ Wu,   const float* __restrict__ bu,
                             const float* __restrict__ Wv,   const float* __restrict__ bv) {
    __shared__ float sg[384], sb[384];
    const int n = blockIdx.x;     // 0..255
    const int c = threadIdx.x;    // 0..383
    float w = (n < 128) ? Wu[c * 128 + n] : Wv[c * 128 + (n - 128)];
    float gw = ln_g[c] * w;
    float bw = ln_b[c] * w;
    float* dst = (c < 128) ? dW1 : ((c < 256) ? dW2 : dWc);
    dst[(c & 127) * 256 + n] = gw;
    sg[c] = gw; sb[c] = bw;
    __syncthreads();
    if (c < 128) {
        sg[c] += sg[c + 128] + sg[c + 256];
        sb[c] += sb[c + 128] + sb[c + 256];
    }
    __syncthreads();
    if (c < 32) {
        float s = sg[c] + sg[c + 32] + sg[c + 64] + sg[c + 96];
        float t = sb[c] + sb[c + 32] + sb[c + 64] + sb[c + 96];
#pragma unroll
        for (int o = 16; o > 0; o >>= 1) {
            s += __shfl_xor_sync(0xffffffffu, s, o);
            t += __shfl_xor_sync(0xffffffffu, t, o);
        }
        if (c == 0) {
            dG[n] = s;
            dB0[n] = t + ((n < 128) ? bu[n] : bv[n - 128]);
        }
    }
}

// ===========================================================================
// Kernel 2: projections. 256 blocks: 0..127 -> q rows, 128..255 -> k rows.
// ===========================================================================
__global__ __launch_bounds__(128, 2)
void proj_kernel(const float* __restrict__ Q, const float* __restrict__ K,
                 const float* __restrict__ Wq, const float* __restrict__ Wk) {
    __shared__ float sh[8 * 1024];  // 32KB
    const int tid = threadIdx.x;
    const int half = blockIdx.x >> 7;            // 0=q, 1=k
    const int r0 = (blockIdx.x & 127) * 8;       // first global row
    const float* src = half ? K : Q;
    const float* W = half ? Wk : Wq;

    {
        const float4* s4 = (const float4*)(src + (size_t)r0 * 1024);
        float4* d4 = (float4*)sh;
        for (int i = tid; i < 2048; i += 128) d4[i] = s4[i];
    }
    __syncthreads();

    float acc[8];
#pragma unroll
    for (int r = 0; r < 8; r++) acc[r] = 0.f;

    for (int d = 0; d < 1024; d += 4) {
        float w0 = W[(d + 0) * 128 + tid];
        float w1 = W[(d + 1) * 128 + tid];
        float w2 = W[(d + 2) * 128 + tid];
        float w3 = W[(d + 3) * 128 + tid];
#pragma unroll
        for (int r = 0; r < 8; r++) {
            float4 qv = *(const float4*)(sh + r * 1024 + d);
            acc[r] = fmaf(qv.x, w0, acc[r]);
            acc[r] = fmaf(qv.y, w1, acc[r]);
            acc[r] = fmaf(qv.z, w2, acc[r]);
            acc[r] = fmaf(qv.w, w3, acc[r]);
        }
    }
    __syncthreads();

    float* outq = half ? d_k : d_q;
#pragma unroll
    for (int r = 0; r < 8; r++) {
        sh[r * 128 + tid] = acc[r];
        outq[(size_t)(r0 + r) * 128 + tid] = acc[r];
    }
    __syncthreads();

    if (tid < 8) {
        float s = 0.f, s2 = 0.f;
        const float* row = sh + tid * 128;
        for (int c = 0; c < 128; c++) {
            float x = row[c];
            s += x;
            s2 = fmaf(x, x, s2);
        }
        if (half) { dsk[r0 + tid] = s; dsk2[r0 + tid] = s2; }
        else      { dsq[r0 + tid] = s; dsq2[r0 + tid] = s2; }
    }

    const float* Wp = half ? dW2 : dW1;
    float au[8], av[8];
#pragma unroll
    for (int r = 0; r < 8; r++) { au[r] = 0.f; av[r] = 0.f; }
    for (int c = 0; c < 128; c++) {
        float wu = Wp[c * 256 + tid];
        float wv = Wp[c * 256 + 128 + tid];
#pragma unroll
        for (int r = 0; r < 8; r++) {
            float qv = sh[r * 128 + c];
            au[r] = fmaf(qv, wu, au[r]);
            av[r] = fmaf(qv, wv, av[r]);
        }
    }
    float* outa = half ? dBk : dAu;
#pragma unroll
    for (int r = 0; r < 8; r++) {
        outa[(size_t)(r0 + r) * 256 + tid] = au[r];
        outa[(size_t)(r0 + r) * 256 + 128 + tid] = av[r];
    }
}

// ===========================================================================
// Kernel 3: main fused kernel. Persistent CTAs (1/SM), 512 threads.
// Tile = 8 i x 8 j; cross GEMM M=64, N=256, K=128 split-K x2 via FFMA2.
// ===========================================================================
#define OFF_WC   0        // 128*256 = 32768
#define OFF_PT   32768    // 128*72 = 9216 floats (P^T; reused as 32KB stage)
#define OFF_TB0  41984    // tile buffer 0
#define OFF_TB1  48224    // tile buffer 1
#define TB_SZ    6240
#define TB_A     0        // 8*256
#define TB_B     2048     // 8*256
#define TB_Q     4096     // 8*132 (padded rows)
#define TB_K     5152     // 8*132
#define TB_SC    6208     // 32 : sq[8] sq2[8] sk[8] sk2[8]
#define OFF_G    54464    // 256
#define OFF_B0   54720    // 256
#define OFF_WO   54976    // 128
#define OFF_RED  55104    // 512
#define OFF_RED2 55616    // 512
#define OFF_R    56128    // 64
#define OFF_NR   56192    // 64
#define SMEM_FLOATS 56256
#define SMEM_MAIN (SMEM_FLOATS * 4)   // 225,024 B

#define NTILES (B_ * 64 * 64)   // 8192

__global__ __launch_bounds__(512, 1)
void main_kernel(const float* __restrict__ Wo, const float* __restrict__ bo,
                 float* __restrict__ out) {
    extern __shared__ float sm[];
    const int tid = threadIdx.x;
    const int tx = tid & 31;          // col group: u cols tx*4..+3, v +128
    const int ty = (tid >> 5) & 7;    // i-row within tile
    const int kh = tid >> 8;          // k-half: 0 -> k 0..63, 1 -> 64..127

    // one-time loads
    {
        float4* wdst = (float4*)(sm + OFF_WC);
        const float4* wsrc = (const float4*)dWc;
        for (int i = tid; i < 8192; i += 512) wdst[i] = wsrc[i];
        if (tid < 256) {
            sm[OFF_G + tid] = dG[tid];
            sm[OFF_B0 + tid] = dB0[tid];
            if (tid < 128) sm[OFF_WO + tid] = Wo[tid];
        }
    }
    __syncthreads();

    const ulonglong2 Gu2  = *(const ulonglong2*)(sm + OFF_G + tx * 4);
    const ulonglong2 Gv2  = *(const ulonglong2*)(sm + OFF_G + 128 + tx * 4);
    const ulonglong2 B0u2 = *(const ulonglong2*)(sm + OFF_B0 + tx * 4);
    const ulonglong2 B0v2 = *(const ulonglong2*)(sm + OFF_B0 + 128 + tx * 4);
    const float4 Wo4 = *(const float4*)(sm + OFF_WO + tx * 4);
    const float bo_v = bo[0];

    const int grid = gridDim.x;

    // ---- initial prefetch of tile t0 into buffer 0 ----
    {
        const int t = blockIdx.x;
        const int b = t >> 12, i0 = ((t >> 6) & 63) * 8, j0 = (t & 63) * 8;
        float* bufn = sm + OFF_TB0;
        ((float4*)(bufn + TB_A))[tid] = ((const float4*)(dAu + (size_t)(b * 512 + i0) * 256))[tid];
        ((float4*)(bufn + TB_B))[tid] = ((const float4*)(dBk + (size_t)(b * 512 + j0) * 256))[tid];
        if (tid < 256) {
            float4 v = ((const float4*)(d_q + (size_t)(b * 512 + i0) * 128))[tid];
            *(float4*)(bufn + TB_Q + (tid >> 5) * 132 + (tid & 31) * 4) = v;
        } else {
            int t2 = tid - 256;
            float4 v = ((const float4*)(d_k + (size_t)(b * 512 + j0) * 128))[t2];
            *(float4*)(bufn + TB_K + (t2 >> 5) * 132 + (t2 & 31) * 4) = v;
        }
        if (tid < 8)       bufn[TB_SC + tid] = dsq [b * 512 + i0 + tid];
        else if (tid < 16) bufn[TB_SC + tid] = dsq2[b * 512 + i0 + tid - 8];
        else if (tid < 24) bufn[TB_SC + tid] = dsk [b * 512 + j0 + tid - 16];
        else if (tid < 32) bufn[TB_SC + tid] = dsk2[b * 512 + j0 + tid - 24];
    }

    int cur = 0;
    for (int t = blockIdx.x; t < NTILES; t += grid) {
        const int b = t >> 12;
        const int i0 = ((t >> 6) & 63) * 8;
        const int j0 = (t & 63) * 8;
        float* bufc = sm + (cur ? OFF_TB1 : OFF_TB0);
        float* bufn = sm + (cur ? OFF_TB0 : OFF_TB1);

        // sync #1: buf[cur] visible; prev tile fully done (incl. stage reads).
        __syncthreads();

        // ---- issue next-tile loads into registers ----
        const int tn = t + grid;
        const bool valid = tn < NTILES;
        float4 ra, rb, rqk;
        float rsc = 0.f;
        if (valid) {
            const int bn = tn >> 12, i0n = ((tn >> 6) & 63) * 8, j0n = (tn & 63) * 8;
            ra = ((const float4*)(dAu + (size_t)(bn * 512 + i0n) * 256))[tid];
            rb = ((const float4*)(dBk + (size_t)(bn * 512 + j0n) * 256))[tid];
            if (tid < 256)
                rqk = ((const float4*)(d_q + (size_t)(bn * 512 + i0n) * 128))[tid];
            else
                rqk = ((const float4*)(d_k + (size_t)(bn * 512 + j0n) * 128))[tid - 256];
            if (tid < 8)       rsc = dsq [bn * 512 + i0n + tid];
            else if (tid < 16) rsc = dsq2[bn * 512 + i0n + tid - 8];
            else if (tid < 24) rsc = dsk [bn * 512 + j0n + tid - 16];
            else if (tid < 32) rsc = dsk2[bn * 512 + j0n + tid - 24];
        }

        // ---- build P^T [c][m] + partial row sums (conflict-free: stride 132)
        {
            const int m = tid & 63, ii = m >> 3, jj = m & 7, c0 = tid >> 6;
            const float* qrow = bufc + TB_Q + ii * 132;
            const float* krow = bufc + TB_K + jj * 132;
            float ls = 0.f, ls2 = 0.f;
#pragma unroll
            for (int s = 0; s < 16; s++) {
                int c = c0 + (s << 3);
                float p = qrow[c] * krow[c];
                sm[OFF_PT + c * 72 + m] = p;
                ls += p;
                ls2 = fmaf(p, p, ls2);
            }
            sm[OFF_RED + tid] = ls;
            sm[OFF_RED2 + tid] = ls2;
        }

        // ---- commit prefetch to buf[nxt] ----
        if (valid) {
            ((float4*)(bufn + TB_A))[tid] = ra;
            ((float4*)(bufn + TB_B))[tid] = rb;
            if (tid < 256)
                *(float4*)(bufn + TB_Q + (tid >> 5) * 132 + (tid & 31) * 4) = rqk;
            else {
                int t2 = tid - 256;
                *(float4*)(bufn + TB_K + (t2 >> 5) * 132 + (t2 & 31) * 4) = rqk;
            }
            if (tid < 32) bufn[TB_SC + tid] = rsc;
        }

        // sync #2: P^T + partials visible.
        __syncthreads();

        // ---- per-pair LN statistics (no barrier needed before GEMM) ----
        if (tid < 64) {
            float s = 0.f, s2 = 0.f;
#pragma unroll
            for (int o = 0; o < 512; o += 64) {
                s  += sm[OFF_RED + o + tid];
                s2 += sm[OFF_RED2 + o + tid];
            }
            int ii = tid >> 3, jj = tid & 7;
            float mu = (bufc[TB_SC + ii] + bufc[TB_SC + 16 + jj] + s) * (1.f / 384.f);
            float e2 = (bufc[TB_SC + 8 + ii] + bufc[TB_SC + 24 + jj] + s2) * (1.f / 384.f);
            float var = e2 - mu * mu;
            float r = rsqrtf(var + EPSV);
            sm[OFF_R + tid] = r;
            sm[OFF_NR + tid] = -r * mu;
        }

        // ---- cross GEMM (this thread's k-half): FFMA2 ----
        ull aU[8][2], aV[8][2];
#pragma unroll
        for (int mi = 0; mi < 8; mi++) {
            aU[mi][0] = 0ull; aU[mi][1] = 0ull;
            aV[mi][0] = 0ull; aV[mi][1] = 0ull;
        }
        const float* ptBase = sm + OFF_PT + (kh << 6) * 72 + ty * 8;
        const float* wB = sm + OFF_WC + (kh << 6) * 256 + tx * 4;
#pragma unroll 4
        for (int kk = 0; kk < 64; kk++) {
            const float4 x0 = *(const float4*)(ptBase + kk * 72);
            const float4 x1 = *(const float4*)(ptBase + kk * 72 + 4);
            const ulonglong2 wu = *(const ulonglong2*)(wB + kk * 256);
            const ulonglong2 wv = *(const ulonglong2*)(wB + kk * 256 + 128);
            float am[8] = {x0.x, x0.y, x0.z, x0.w, x1.x, x1.y, x1.z, x1.w};
#pragma unroll
            for (int mi = 0; mi < 8; mi++) {
                ull a2 = pack2(am[mi]);
                FMA2(aU[mi][0], a2, wu.x);
                FMA2(aU[mi][1], a2, wu.y);
                FMA2(aV[mi][0], a2, wv.x);
                FMA2(aV[mi][1], a2, wv.y);
            }
        }

        // ---- split-K combine via smem stage (reuses P^T region) ----
        // each thread KEEPS mi in [kh*4, kh*4+4), GIVES the other 4 to partner
        ull* stg = (ull*)(sm + OFF_PT);
        const int give = (1 - kh) * 4;
        const int keep = kh * 4;
        const int partner = tid ^ 256;

        // sync #3: all GEMM reads of P^T done before staging overwrites it.
        __syncthreads();
#pragma unroll
        for (int m2 = 0; m2 < 4; m2++) {
            stg[tid * 8 + m2 * 2]     = aU[give + m2][0];
            stg[tid * 8 + m2 * 2 + 1] = aU[give + m2][1];
        }
        __syncthreads();  // #4
#pragma unroll
        for (int m2 = 0; m2 < 4; m2++) {
            aU[keep + m2][0] = add2(aU[keep + m2][0], stg[partner * 8 + m2 * 2]);
            aU[keep + m2][1] = add2(aU[keep + m2][1], stg[partner * 8 + m2 * 2 + 1]);
        }
        __syncthreads();  // #5
#pragma unroll
        for (int m2 = 0; m2 < 4; m2++) {
            stg[tid * 8 + m2 * 2]     = aV[give + m2][0];
            stg[tid * 8 + m2 * 2 + 1] = aV[give + m2][1];
        }
        __syncthreads();  // #6
#pragma unroll
        for (int m2 = 0; m2 < 4; m2++) {
            aV[keep + m2][0] = add2(aV[keep + m2][0], stg[partner * 8 + m2 * 2]);
            aV[keep + m2][1] = add2(aV[keep + m2][1], stg[partner * 8 + m2 * 2 + 1]);
        }

        // ---- fused epilogue (4 pairs per thread): LN + erf-gelu + Wo dot ----
        const ulonglong2 au2 = *(const ulonglong2*)(bufc + TB_A + ty * 256 + tx * 4);
        const ulonglong2 av2 = *(const ulonglong2*)(bufc + TB_A + ty * 256 + 128 + tx * 4);
#pragma unroll
        for (int m2 = 0; m2 < 4; m2++) {
            const int mi = keep + m2;
            const int m = ty * 8 + mi;
            const ull r2  = pack2(sm[OFF_R + m]);
            const ull nr2 = pack2(sm[OFF_NR + m]);
            const ulonglong2 bu2 = *(const ulonglong2*)(bufc + TB_B + mi * 256 + tx * 4);
            const ulonglong2 bv2 = *(const ulonglong2*)(bufc + TB_B + mi * 256 + 128 + tx * 4);
            ull u0 = fma2n(r2, add2(add2(au2.x, bu2.x), aU[mi][0]),
                           fma2n(nr2, Gu2.x, B0u2.x));
            ull u1 = fma2n(r2, add2(add2(au2.y, bu2.y), aU[mi][1]),
                           fma2n(nr2, Gu2.y, B0u2.y));
            ull v0 = fma2n(r2, add2(add2(av2.x, bv2.x), aV[mi][0]),
                           fma2n(nr2, Gv2.x, B0v2.x));
            ull v1 = fma2n(r2, add2(add2(av2.y, bv2.y), aV[mi][1]),
                           fma2n(nr2, Gv2.y, B0v2.y));
            float ua, ub, uc, ud, va, vb, vc, vd;
            unpack2(u0, ua, ub); unpack2(u1, uc, ud);
            unpack2(v0, va, vb); unpack2(v1, vc, vd);
            float pd;
            pd = (ua * gelu_ex(va)) * Wo4.x;
            pd = fmaf(ub * gelu_ex(vb), Wo4.y, pd);
            pd = fmaf(uc * gelu_ex(vc), Wo4.z, pd);
            pd = fmaf(ud * gelu_ex(vd), Wo4.w, pd);
#pragma unroll
            for (int o = 16; o > 0; o >>= 1)
                pd += __shfl_xor_sync(0xffffffffu, pd, o);
            if (tx == 0)
                out[((size_t)(b * 512 + i0 + ty)) * 512 + j0 + mi] = pd + bo_v;
        }

        cur ^= 1;
    }
}

// ===========================================================================
// launcher
// ===========================================================================
extern "C" void kernel_launch(void* const* d_in, const int* in_sizes, int n_in,
                              void* d_out, int out_size) {
    const float* Q    = (const float*)d_in[0];
    const float* K    = (const float*)d_in[1];
    const float* Wq   = (const float*)d_in[2];
    const float* Wk   = (const float*)d_in[3];
    const float* ln_g = (const float*)d_in[4];
    const float* ln_b = (const float*)d_in[5];
    const float* Wu   = (const float*)d_in[6];
    const float* bu   = (const float*)d_in[7];
    const float* Wv   = (const float*)d_in[8];
    const float* bv   = (const float*)d_in[9];
    const float* Wo   = (const float*)d_in[10];
    const float* bo   = (const float*)d_in[11];
    float* out = (float*)d_out;

    int nsm = 148;
    cudaDeviceGetAttribute(&nsm, cudaDevAttrMultiProcessorCount, 0);

    cudaFuncSetAttribute(main_kernel, cudaFuncAttributeMaxDynamicSharedMemorySize, SMEM_MAIN);

    deriv_kernel<<<256, 384>>>(ln_g, ln_b, Wu, bu, Wv, bv);
    proj_kernel<<<256, 128>>>(Q, K, Wq, Wk);
    main_kernel<<<nsm, 512, SMEM_MAIN>>>(Wo, bo, out);
}

// round 10
// speedup vs baseline: 1.4046x; 1.4046x over previous
#include <cuda_runtime.h>
#include <cstdint>
#include <cstddef>

// ---------------------------------------------------------------------------
// FullAttentionEstimator: B=2, Tq=Tk=512, Q_DIM=K_DIM=1024, HID=128
//
// Factorization:
//   q = Q@Wq, k = K@Wk                       (per-row, precomputed)
//   x = [q, k, q*k]  (384)
//   LN(x)@W = r*(x@(g.W)) - r*mu*(g@W) + (b@W + bias)
//   x@(g.W) = q@W1 + k@W2 + p@W3,  p = q*k  (per pair)
// Cross term p@W3 is an fp32 GEMM with packed fma.rn.f32x2 (FFMA2),
// 256-thread persistent CTAs (pipe-saturating: 2 warps/SMSP x 32 FFMA2/k
// fills the rt=2 FMA pipe); per-tile operands double-buffered; q/k tile rows
// padded to stride 132 (conflict-free P build); epilogue fuses LN recombine
// (f32x2-packed) + erf-based exact gelu + Wo dot.
// ---------------------------------------------------------------------------

#define B_    2
#define HID_  128
#define EPSV  1e-5f

typedef unsigned long long ull;

// -------------------- device scratch (no allocations allowed) --------------
__device__ float dW1[128 * 256];     // g-scaled Wu|Wv rows 0..127   [c][n]
__device__ float dW2[128 * 256];     // rows 128..255
__device__ float dWc[128 * 256];     // rows 256..383 (cross weights)
__device__ float dG[256];            // sum_c g_c W[c][n]
__device__ float dB0[256];           // sum_c b_c W[c][n] + bias[n]
__device__ float d_q[1024 * 128];    // projected q rows (B*Tq)
__device__ float d_k[1024 * 128];
__device__ float dAu[1024 * 256];    // q@W1 (u|v)
__device__ float dBk[1024 * 256];    // k@W2 (u|v)
__device__ float dsq[1024], dsq2[1024], dsk[1024], dsk2[1024];

// -------------------- packed f32x2 helpers ---------------------------------
__device__ __forceinline__ ull pack2(float x) {
    ull r;
    asm("mov.b64 %0, {%1, %1};" : "=l"(r) : "r"(__float_as_uint(x)));
    return r;
}
__device__ __forceinline__ void unpack2(ull v, float& lo, float& hi) {
    asm("mov.b64 {%0, %1}, %2;" : "=f"(lo), "=f"(hi) : "l"(v));
}
__device__ __forceinline__ ull add2(ull a, ull b) {
    ull r;
    asm("add.rn.f32x2 %0, %1, %2;" : "=l"(r) : "l"(a), "l"(b));
    return r;
}
__device__ __forceinline__ ull fma2n(ull a, ull b, ull c) {
    ull r;
    asm("fma.rn.f32x2 %0, %1, %2, %3;" : "=l"(r) : "l"(a), "l"(b), "l"(c));
    return r;
}
#define FMA2(acc, a, b) \
    asm("fma.rn.f32x2 %0, %1, %2, %0;" : "+l"(acc) : "l"(a), "l"(b))

__device__ __forceinline__ float gelu_ex(float v) {
    // exact gelu: v * Phi(v); erff is branch-free & ~2-ulp accurate
    return v * (0.5f + 0.5f * erff(v * 0.70710678118654752f));
}

// ===========================================================================
// Kernel 1: derived weights. 256 blocks (one per output col n), 384 threads.
// ===========================================================================
__global__ void deriv_kernel(const float* __restrict__ ln_g, const float* __restrict__ ln_b,
                             const float* __restrict__ Wu,   const float* __restrict__ bu,
                             const float* __restrict__ Wv,   const float* __restrict__ bv) {
    __shared__ float sg[384], sb[384];
    const int n = blockIdx.x;     // 0..255
    const int c = threadIdx.x;    // 0..383
    float w = (n < 128) ? Wu[c * 128 + n] : Wv[c * 128 + (n - 128)];
    float gw = ln_g[c] * w;
    float bw = ln_b[c] * w;
    float* dst = (c < 128) ? dW1 : ((c < 256) ? dW2 : dWc);
    dst[(c & 127) * 256 + n] = gw;
    sg[c] = gw; sb[c] = bw;
    __syncthreads();
    if (c < 128) {
        sg[c] += sg[c + 128] + sg[c + 256];
        sb[c] += sb[c + 128] + sb[c + 256];
    }
    __syncthreads();
    if (c < 32) {
        float s = sg[c] + sg[c + 32] + sg[c + 64] + sg[c + 96];
        float t = sb[c] + sb[c + 32] + sb[c + 64] + sb[c + 96];
#pragma unroll
        for (int o = 16; o > 0; o >>= 1) {
            s += __shfl_xor_sync(0xffffffffu, s, o);
            t += __shfl_xor_sync(0xffffffffu, t, o);
        }
        if (c == 0) {
            dG[n] = s;
            dB0[n] = t + ((n < 128) ? bu[n] : bv[n - 128]);
        }
    }
}

// ===========================================================================
// Kernel 2: projections. 256 blocks: 0..127 -> q rows, 128..255 -> k rows.
// ===========================================================================
__global__ __launch_bounds__(128, 2)
void proj_kernel(const float* __restrict__ Q, const float* __restrict__ K,
                 const float* __restrict__ Wq, const float* __restrict__ Wk) {
    __shared__ float sh[8 * 1024];  // 32KB
    const int tid = threadIdx.x;
    const int half = blockIdx.x >> 7;            // 0=q, 1=k
    const int r0 = (blockIdx.x & 127) * 8;       // first global row
    const float* src = half ? K : Q;
    const float* W = half ? Wk : Wq;

    {
        const float4* s4 = (const float4*)(src + (size_t)r0 * 1024);
        float4* d4 = (float4*)sh;
        for (int i = tid; i < 2048; i += 128) d4[i] = s4[i];
    }
    __syncthreads();

    float acc[8];
#pragma unroll
    for (int r = 0; r < 8; r++) acc[r] = 0.f;

    for (int d = 0; d < 1024; d += 4) {
        float w0 = W[(d + 0) * 128 + tid];
        float w1 = W[(d + 1) * 128 + tid];
        float w2 = W[(d + 2) * 128 + tid];
        float w3 = W[(d + 3) * 128 + tid];
#pragma unroll
        for (int r = 0; r < 8; r++) {
            float4 qv = *(const float4*)(sh + r * 1024 + d);
            acc[r] = fmaf(qv.x, w0, acc[r]);
            acc[r] = fmaf(qv.y, w1, acc[r]);
            acc[r] = fmaf(qv.z, w2, acc[r]);
            acc[r] = fmaf(qv.w, w3, acc[r]);
        }
    }
    __syncthreads();

    float* outq = half ? d_k : d_q;
#pragma unroll
    for (int r = 0; r < 8; r++) {
        sh[r * 128 + tid] = acc[r];
        outq[(size_t)(r0 + r) * 128 + tid] = acc[r];
    }
    __syncthreads();

    if (tid < 8) {
        float s = 0.f, s2 = 0.f;
        const float* row = sh + tid * 128;
        for (int c = 0; c < 128; c++) {
            float x = row[c];
            s += x;
            s2 = fmaf(x, x, s2);
        }
        if (half) { dsk[r0 + tid] = s; dsk2[r0 + tid] = s2; }
        else      { dsq[r0 + tid] = s; dsq2[r0 + tid] = s2; }
    }

    const float* Wp = half ? dW2 : dW1;
    float au[8], av[8];
#pragma unroll
    for (int r = 0; r < 8; r++) { au[r] = 0.f; av[r] = 0.f; }
    for (int c = 0; c < 128; c++) {
        float wu = Wp[c * 256 + tid];
        float wv = Wp[c * 256 + 128 + tid];
#pragma unroll
        for (int r = 0; r < 8; r++) {
            float qv = sh[r * 128 + c];
            au[r] = fmaf(qv, wu, au[r]);
            av[r] = fmaf(qv, wv, av[r]);
        }
    }
    float* outa = half ? dBk : dAu;
#pragma unroll
    for (int r = 0; r < 8; r++) {
        outa[(size_t)(r0 + r) * 256 + tid] = au[r];
        outa[(size_t)(r0 + r) * 256 + 128 + tid] = av[r];
    }
}

// ===========================================================================
// Kernel 3: main fused kernel. Persistent CTAs (1/SM), 256 threads.
// Tile = 8 i x 8 j = 64 pairs; cross GEMM M=64, N=256, K=128 via FFMA2.
// q/k tile rows padded to 132 floats -> conflict-free P build.
// ===========================================================================
#define OFF_WC   0        // 128*256 = 32768
#define OFF_PT   32768    // 128*72  = 9216  (p transposed, padded rows)
#define OFF_TB0  41984    // tile buffer 0 (6240 floats)
#define OFF_TB1  48224    // tile buffer 1
#define TB_SZ    6240
#define TB_A     0        // 8*256
#define TB_B     2048     // 8*256
#define TB_Q     4096     // 8*132 (padded rows)
#define TB_K     5152     // 8*132
#define TB_SC    6208     // 32 : sq[8] sq2[8] sk[8] sk2[8]
#define OFF_G    54464    // 256
#define OFF_B0   54720    // 256
#define OFF_WO   54976    // 128
#define OFF_RED  55104    // 256
#define OFF_RED2 55360    // 256
#define OFF_R    55616    // 64
#define OFF_NR   55680    // 64
#define SMEM_FLOATS 55744
#define SMEM_MAIN (SMEM_FLOATS * 4)   // 222,976 B

#define NTILES (B_ * 64 * 64)   // 8192

__global__ __launch_bounds__(256, 1)
void main_kernel(const float* __restrict__ Wo, const float* __restrict__ bo,
                 float* __restrict__ out) {
    extern __shared__ float sm[];
    const int tid = threadIdx.x;
    const int tx = tid & 31;   // N-group: u cols tx*4..+3, v cols 128+tx*4..+3
    const int ty = tid >> 5;   // i-row within tile

    // one-time loads: cross weights + G/B0/Wo
    {
        float4* wdst = (float4*)(sm + OFF_WC);
        const float4* wsrc = (const float4*)dWc;
        for (int i = tid; i < 8192; i += 256) wdst[i] = wsrc[i];
        sm[OFF_G + tid] = dG[tid];
        sm[OFF_B0 + tid] = dB0[tid];
        if (tid < 128) sm[OFF_WO + tid] = Wo[tid];
    }
    __syncthreads();

    const ulonglong2 Gu2  = *(const ulonglong2*)(sm + OFF_G + tx * 4);
    const ulonglong2 Gv2  = *(const ulonglong2*)(sm + OFF_G + 128 + tx * 4);
    const ulonglong2 B0u2 = *(const ulonglong2*)(sm + OFF_B0 + tx * 4);
    const ulonglong2 B0v2 = *(const ulonglong2*)(sm + OFF_B0 + 128 + tx * 4);
    const float4 Wo4 = *(const float4*)(sm + OFF_WO + tx * 4);
    const float bo_v = bo[0];

    const int grid = gridDim.x;

    // ---- initial prefetch of tile t0 into buffer 0 ----
    {
        const int t = blockIdx.x;
        const int b = t >> 12, i0 = ((t >> 6) & 63) * 8, j0 = (t & 63) * 8;
        float* bufn = sm + OFF_TB0;
        float4 vq = ((const float4*)(d_q + (size_t)(b * 512 + i0) * 128))[tid];
        float4 vk = ((const float4*)(d_k + (size_t)(b * 512 + j0) * 128))[tid];
        *(float4*)(bufn + TB_Q + (tid >> 5) * 132 + (tid & 31) * 4) = vq;
        *(float4*)(bufn + TB_K + (tid >> 5) * 132 + (tid & 31) * 4) = vk;
        const float4* ag = (const float4*)(dAu + (size_t)(b * 512 + i0) * 256);
        ((float4*)(bufn + TB_A))[tid] = ag[tid];
        ((float4*)(bufn + TB_A))[256 + tid] = ag[256 + tid];
        const float4* bg = (const float4*)(dBk + (size_t)(b * 512 + j0) * 256);
        ((float4*)(bufn + TB_B))[tid] = bg[tid];
        ((float4*)(bufn + TB_B))[256 + tid] = bg[256 + tid];
        if (tid < 8)       bufn[TB_SC + tid] = dsq [b * 512 + i0 + tid];
        else if (tid < 16) bufn[TB_SC + tid] = dsq2[b * 512 + i0 + tid - 8];
        else if (tid < 24) bufn[TB_SC + tid] = dsk [b * 512 + j0 + tid - 16];
        else if (tid < 32) bufn[TB_SC + tid] = dsk2[b * 512 + j0 + tid - 24];
    }

    int cur = 0;
    for (int t = blockIdx.x; t < NTILES; t += grid) {
        const int b = t >> 12;
        const int i0 = ((t >> 6) & 63) * 8;
        const int j0 = (t & 63) * 8;
        float* bufc = sm + (cur ? OFF_TB1 : OFF_TB0);
        float* bufn = sm + (cur ? OFF_TB0 : OFF_TB1);

        // sync #1: prefetched buf[cur] visible; previous tile done with smem.
        __syncthreads();

        // ---- issue next-tile loads into registers (latency overlaps build) --
        const int tn = t + grid;
        const bool valid = tn < NTILES;
        float4 rq, rk, ra0, ra1, rb0, rb1;
        float rsc = 0.f;
        if (valid) {
            const int bn = tn >> 12, i0n = ((tn >> 6) & 63) * 8, j0n = (tn & 63) * 8;
            rq  = ((const float4*)(d_q + (size_t)(bn * 512 + i0n) * 128))[tid];
            rk  = ((const float4*)(d_k + (size_t)(bn * 512 + j0n) * 128))[tid];
            const float4* ag = (const float4*)(dAu + (size_t)(bn * 512 + i0n) * 256);
            ra0 = ag[tid]; ra1 = ag[256 + tid];
            const float4* bg = (const float4*)(dBk + (size_t)(bn * 512 + j0n) * 256);
            rb0 = bg[tid]; rb1 = bg[256 + tid];
            if (tid < 8)       rsc = dsq [bn * 512 + i0n + tid];
            else if (tid < 16) rsc = dsq2[bn * 512 + i0n + tid - 8];
            else if (tid < 24) rsc = dsk [bn * 512 + j0n + tid - 16];
            else if (tid < 32) rsc = dsk2[bn * 512 + j0n + tid - 24];
        }

        // ---- build P^T [c][m] + partial row sums (conflict-free, stride 132)
        {
            const int m = tid & 63, ii = m >> 3, jj = m & 7, c0 = tid >> 6;
            const float* qrow = bufc + TB_Q + ii * 132;
            const float* krow = bufc + TB_K + jj * 132;
            float ls = 0.f, ls2 = 0.f;
#pragma unroll
            for (int s = 0; s < 32; s++) {
                int c = c0 + (s << 2);
                float p = qrow[c] * krow[c];
                sm[OFF_PT + c * 72 + m] = p;
                ls += p;
                ls2 = fmaf(p, p, ls2);
            }
            sm[OFF_RED + tid] = ls;
            sm[OFF_RED2 + tid] = ls2;
        }

        // ---- commit prefetch to buf[nxt] ----
        if (valid) {
            *(float4*)(bufn + TB_Q + (tid >> 5) * 132 + (tid & 31) * 4) = rq;
            *(float4*)(bufn + TB_K + (tid >> 5) * 132 + (tid & 31) * 4) = rk;
            ((float4*)(bufn + TB_A))[tid] = ra0;
            ((float4*)(bufn + TB_A))[256 + tid] = ra1;
            ((float4*)(bufn + TB_B))[tid] = rb0;
            ((float4*)(bufn + TB_B))[256 + tid] = rb1;
            if (tid < 32) bufn[TB_SC + tid] = rsc;
        }

        // sync #2: P^T + partials (and prefetch STS) visible.
        __syncthreads();

        // ---- per-pair LN statistics ----
        if (tid < 64) {
            float s = sm[OFF_RED + tid] + sm[OFF_RED + 64 + tid] +
                      sm[OFF_RED + 128 + tid] + sm[OFF_RED + 192 + tid];
            float s2 = sm[OFF_RED2 + tid] + sm[OFF_RED2 + 64 + tid] +
                       sm[OFF_RED2 + 128 + tid] + sm[OFF_RED2 + 192 + tid];
            int ii = tid >> 3, jj = tid & 7;
            float mu = (bufc[TB_SC + ii] + bufc[TB_SC + 16 + jj] + s) * (1.f / 384.f);
            float e2 = (bufc[TB_SC + 8 + ii] + bufc[TB_SC + 24 + jj] + s2) * (1.f / 384.f);
            float var = e2 - mu * mu;
            float r = rsqrtf(var + EPSV);
            sm[OFF_R + tid] = r;
            sm[OFF_NR + tid] = -r * mu;
        }
        // sync #3: stats visible.
        __syncthreads();

        // ---- cross GEMM: C[64x256] = P[64x128] @ Wc[128x256] via FFMA2 ----
        ull aU[8][2], aV[8][2];
#pragma unroll
        for (int mi = 0; mi < 8; mi++) {
            aU[mi][0] = 0ull; aU[mi][1] = 0ull;
            aV[mi][0] = 0ull; aV[mi][1] = 0ull;
        }
        const float* ptBase = sm + OFF_PT + ty * 8;
        const float* wB = sm + OFF_WC + tx * 4;
#pragma unroll 2
        for (int k = 0; k < 128; k++) {
            const float4 x0 = *(const float4*)(ptBase + k * 72);
            const float4 x1 = *(const float4*)(ptBase + k * 72 + 4);
            const ulonglong2 wu = *(const ulonglong2*)(wB + k * 256);
            const ulonglong2 wv = *(const ulonglong2*)(wB + k * 256 + 128);
            float am[8] = {x0.x, x0.y, x0.z, x0.w, x1.x, x1.y, x1.z, x1.w};
#pragma unroll
            for (int mi = 0; mi < 8; mi++) {
                ull a2 = pack2(am[mi]);
                FMA2(aU[mi][0], a2, wu.x);
                FMA2(aU[mi][1], a2, wu.y);
                FMA2(aV[mi][0], a2, wv.x);
                FMA2(aV[mi][1], a2, wv.y);
            }
        }

        // ---- fused epilogue: packed LN recombine + erf-gelu + Wo dot ----
        const ulonglong2 au2 = *(const ulonglong2*)(bufc + TB_A + ty * 256 + tx * 4);
        const ulonglong2 av2 = *(const ulonglong2*)(bufc + TB_A + ty * 256 + 128 + tx * 4);
#pragma unroll
        for (int mi = 0; mi < 8; mi++) {
            const int m = ty * 8 + mi;
            const ull r2  = pack2(sm[OFF_R + m]);
            const ull nr2 = pack2(sm[OFF_NR + m]);
            const ulonglong2 bu2 = *(const ulonglong2*)(bufc + TB_B + mi * 256 + tx * 4);
            const ulonglong2 bv2 = *(const ulonglong2*)(bufc + TB_B + mi * 256 + 128 + tx * 4);
            ull u0 = fma2n(r2, add2(add2(au2.x, bu2.x), aU[mi][0]),
                           fma2n(nr2, Gu2.x, B0u2.x));
            ull u1 = fma2n(r2, add2(add2(au2.y, bu2.y), aU[mi][1]),
                           fma2n(nr2, Gu2.y, B0u2.y));
            ull v0 = fma2n(r2, add2(add2(av2.x, bv2.x), aV[mi][0]),
                           fma2n(nr2, Gv2.x, B0v2.x));
            ull v1 = fma2n(r2, add2(add2(av2.y, bv2.y), aV[mi][1]),
                           fma2n(nr2, Gv2.y, B0v2.y));
            float ua, ub, uc, ud, va, vb, vc, vd;
            unpack2(u0, ua, ub); unpack2(u1, uc, ud);
            unpack2(v0, va, vb); unpack2(v1, vc, vd);
            float pd;
            pd = (ua * gelu_ex(va)) * Wo4.x;
            pd = fmaf(ub * gelu_ex(vb), Wo4.y, pd);
            pd = fmaf(uc * gelu_ex(vc), Wo4.z, pd);
            pd = fmaf(ud * gelu_ex(vd), Wo4.w, pd);
#pragma unroll
            for (int o = 16; o > 0; o >>= 1)
                pd += __shfl_xor_sync(0xffffffffu, pd, o);
            if (tx == 0)
                out[((size_t)(b * 512 + i0 + ty)) * 512 + j0 + mi] = pd + bo_v;
        }

        cur ^= 1;
    }
}

// ===========================================================================
// launcher
// ===========================================================================
extern "C" void kernel_launch(void* const* d_in, const int* in_sizes, int n_in,
                              void* d_out, int out_size) {
    const float* Q    = (const float*)d_in[0];
    const float* K    = (const float*)d_in[1];
    const float* Wq   = (const float*)d_in[2];
    const float* Wk   = (const float*)d_in[3];
    const float* ln_g = (const float*)d_in[4];
    const float* ln_b = (const float*)d_in[5];
    const float* Wu   = (const float*)d_in[6];
    const float* bu   = (const float*)d_in[7];
    const float* Wv   = (const float*)d_in[8];
    const float* bv   = (const float*)d_in[9];
    const float* Wo   = (const float*)d_in[10];
    const float* bo   = (const float*)d_in[11];
    float* out = (float*)d_out;

    int nsm = 148;
    cudaDeviceGetAttribute(&nsm, cudaDevAttrMultiProcessorCount, 0);

    cudaFuncSetAttribute(main_kernel, cudaFuncAttributeMaxDynamicSharedMemorySize, SMEM_MAIN);

    deriv_kernel<<<256, 384>>>(ln_g, ln_b, Wu, bu, Wv, bv);
    proj_kernel<<<256, 128>>>(Q, K, Wq, Wk);
    main_kernel<<<nsm, 256, SMEM_MAIN>>>(Wo, bo, out);
}

// round 13
// speedup vs baseline: 2.4813x; 1.7665x over previous
#include <cuda_runtime.h>
#include <cuda_bf16.h>
#include <cstdint>
#include <cstddef>

// ---------------------------------------------------------------------------
// FullAttentionEstimator: B=2, Tq=Tk=512, Q_DIM=K_DIM=1024, HID=128
//
// Factorization:
//   q = Q@Wq, k = K@Wk                       (per-row, precomputed)
//   x = [q, k, q*k]  (384)
//   LN(x)@W = r*(x@(g.W)) - r*mu*(g@W) + (b@W + bias)
//   x@(g.W) = q@W1 + k@W2 + p@W3,  p = q*k  (per pair)
// Cross term p@W3: legacy tensor-core path (mma.sync m16n8k16 bf16 — plain
// sm_80+ PTX; tcgen05 is NOT available at the bench's compute_103 target),
// with 3-pass bf16x3 splitting (p_hi@W_hi + p_hi@W_lo + p_lo@W_hi) into
// register fp32 accumulators. Tile = 64 pairs x 256 cols x K=128.
// Epilogue fuses LN recombine + erf-gelu + Wo dot directly on the accums.
// ---------------------------------------------------------------------------

#define EPSV   1e-5f
#define NTILES 8192          // 2 batches * 64 i-tiles(8) * 64 j-tiles(8)

// -------------------- device scratch (no allocations allowed) --------------
__device__ float dW1[128 * 256];     // g-scaled Wu|Wv rows 0..127   [c][n]
__device__ float dW2[128 * 256];     // rows 128..255
__device__ float dG[256];            // sum_c g_c W[c][n]
__device__ float dB0[256];           // sum_c b_c W[c][n] + bias[n]
__device__ uint4 dWcT_hi[4096];      // cross weights bf16 hi, [n=256][k=128]
__device__ uint4 dWcT_lo[4096];      // cross weights bf16 lo
__device__ float d_q[1024 * 128];    // projected q rows (B*Tq)
__device__ float d_k[1024 * 128];
__device__ float dAu[1024 * 256];    // q@W1 (u|v)
__device__ float dBk[1024 * 256];    // k@W2 (u|v)
__device__ float dsq[1024], dsq2[1024], dsk[1024], dsk2[1024];

// -------------------- helpers ----------------------------------------------
__device__ __forceinline__ uint32_t smem_u32(const void* p) {
    uint32_t a;
    asm("{ .reg .u64 t; cvta.to.shared.u64 t, %1; cvt.u32.u64 %0, t; }"
        : "=r"(a) : "l"(p));
    return a;
}

__device__ __forceinline__ void ldsm4(uint32_t* r, uint32_t addr) {
    asm volatile("ldmatrix.sync.aligned.m8n8.x4.shared.b16 {%0,%1,%2,%3}, [%4];"
                 : "=r"(r[0]), "=r"(r[1]), "=r"(r[2]), "=r"(r[3]) : "r"(addr));
}

__device__ __forceinline__ void hmma(float* d, const uint32_t* a,
                                     uint32_t b0, uint32_t b1) {
    asm volatile(
        "mma.sync.aligned.m16n8k16.row.col.f32.bf16.bf16.f32 "
        "{%0,%1,%2,%3}, {%4,%5,%6,%7}, {%8,%9}, {%0,%1,%2,%3};"
        : "+f"(d[0]), "+f"(d[1]), "+f"(d[2]), "+f"(d[3])
        : "r"(a[0]), "r"(a[1]), "r"(a[2]), "r"(a[3]), "r"(b0), "r"(b1));
}

__device__ __forceinline__ float gelu_ex(float v) {
    return v * (0.5f + 0.5f * erff(v * 0.70710678118654752f));
}

// ===========================================================================
// Kernel 1: derived weights. 256 blocks (col n), 384 threads (channel c).
// Cross rows (c>=256) written transposed [n][k], bf16 hi/lo split.
// ===========================================================================
__global__ void deriv_kernel(const float* __restrict__ ln_g, const float* __restrict__ ln_b,
                             const float* __restrict__ Wu,   const float* __restrict__ bu,
                             const float* __restrict__ Wv,   const float* __restrict__ bv) {
    __shared__ float sg[384], sb[384];
    const int n = blockIdx.x;     // 0..255
    const int c = threadIdx.x;    // 0..383
    float w = (n < 128) ? Wu[c * 128 + n] : Wv[c * 128 + (n - 128)];
    float gw = ln_g[c] * w;
    float bw = ln_b[c] * w;
    if (c < 128)      dW1[c * 256 + n] = gw;
    else if (c < 256) dW2[(c - 128) * 256 + n] = gw;
    else {
        int k = c - 256;
        __nv_bfloat16 hi = __float2bfloat16(gw);
        __nv_bfloat16 lo = __float2bfloat16(gw - __bfloat162float(hi));
        ((__nv_bfloat16*)dWcT_hi)[n * 128 + k] = hi;
        ((__nv_bfloat16*)dWcT_lo)[n * 128 + k] = lo;
    }
    sg[c] = gw; sb[c] = bw;
    __syncthreads();
    if (c < 128) {
        sg[c] += sg[c + 128] + sg[c + 256];
        sb[c] += sb[c + 128] + sb[c + 256];
    }
    __syncthreads();
    if (c < 32) {
        float s = sg[c] + sg[c + 32] + sg[c + 64] + sg[c + 96];
        float t = sb[c] + sb[c + 32] + sb[c + 64] + sb[c + 96];
#pragma unroll
        for (int o = 16; o > 0; o >>= 1) {
            s += __shfl_xor_sync(0xffffffffu, s, o);
            t += __shfl_xor_sync(0xffffffffu, t, o);
        }
        if (c == 0) {
            dG[n] = s;
            dB0[n] = t + ((n < 128) ? bu[n] : bv[n - 128]);
        }
    }
}

// ===========================================================================
// Kernel 2: projections. 256 blocks: 0..127 -> q rows, 128..255 -> k rows.
// ===========================================================================
__global__ __launch_bounds__(128, 2)
void proj_kernel(const float* __restrict__ Q, const float* __restrict__ K,
                 const float* __restrict__ Wq, const float* __restrict__ Wk) {
    __shared__ float sh[8 * 1024];  // 32KB
    const int tid = threadIdx.x;
    const int half = blockIdx.x >> 7;
    const int r0 = (blockIdx.x & 127) * 8;
    const float* src = half ? K : Q;
    const float* W = half ? Wk : Wq;

    {
        const float4* s4 = (const float4*)(src + (size_t)r0 * 1024);
        float4* d4 = (float4*)sh;
        for (int i = tid; i < 2048; i += 128) d4[i] = s4[i];
    }
    __syncthreads();

    float acc[8];
#pragma unroll
    for (int r = 0; r < 8; r++) acc[r] = 0.f;

    for (int d = 0; d < 1024; d += 4) {
        float w0 = W[(d + 0) * 128 + tid];
        float w1 = W[(d + 1) * 128 + tid];
        float w2 = W[(d + 2) * 128 + tid];
        float w3 = W[(d + 3) * 128 + tid];
#pragma unroll
        for (int r = 0; r < 8; r++) {
            float4 qv = *(const float4*)(sh + r * 1024 + d);
            acc[r] = fmaf(qv.x, w0, acc[r]);
            acc[r] = fmaf(qv.y, w1, acc[r]);
            acc[r] = fmaf(qv.z, w2, acc[r]);
            acc[r] = fmaf(qv.w, w3, acc[r]);
        }
    }
    __syncthreads();

    float* outq = half ? d_k : d_q;
#pragma unroll
    for (int r = 0; r < 8; r++) {
        sh[r * 128 + tid] = acc[r];
        outq[(size_t)(r0 + r) * 128 + tid] = acc[r];
    }
    __syncthreads();

    if (tid < 8) {
        float s = 0.f, s2 = 0.f;
        const float* row = sh + tid * 128;
        for (int c = 0; c < 128; c++) {
            float x = row[c];
            s += x;
            s2 = fmaf(x, x, s2);
        }
        if (half) { dsk[r0 + tid] = s; dsk2[r0 + tid] = s2; }
        else      { dsq[r0 + tid] = s; dsq2[r0 + tid] = s2; }
    }

    const float* Wp = half ? dW2 : dW1;
    float au[8], av[8];
#pragma unroll
    for (int r = 0; r < 8; r++) { au[r] = 0.f; av[r] = 0.f; }
    for (int c = 0; c < 128; c++) {
        float wu = Wp[c * 256 + tid];
        float wv = Wp[c * 256 + 128 + tid];
#pragma unroll
        for (int r = 0; r < 8; r++) {
            float qv = sh[r * 128 + c];
            au[r] = fmaf(qv, wu, au[r]);
            av[r] = fmaf(qv, wv, av[r]);
        }
    }
    float* outa = half ? dBk : dAu;
#pragma unroll
    for (int r = 0; r < 8; r++) {
        outa[(size_t)(r0 + r) * 256 + tid] = au[r];
        outa[(size_t)(r0 + r) * 256 + 128 + tid] = av[r];
    }
}

// ===========================================================================
// Kernel 3: mma.sync main kernel. Persistent CTAs (1/SM), 256 threads.
// Tile = 64 pairs (8i x 8j) x N=256 (u|v) x K=128.
// Warp w: all 64 rows, u-cols [w*16, w*16+16) + v-cols [128+w*16, ...).
// ===========================================================================
// smem byte offsets
#define WHI_O   0          // 65536 : Wc^T hi bf16 [256 n-rows x 128 k] swizzled
#define WLO_O   65536      // 65536 : Wc^T lo
#define PHI_O   131072     // 16384 : P hi bf16 [64 m-rows x 128 k] swizzled
#define PLO_O   147456     // 16384 : P lo
// float offsets (region starts at byte 163840)
#define AU_F    40960      // 8 x 260
#define BK_F    43040      // 8 x 260
#define QS_F    45120      // 8 x 132
#define KS_F    46176      // 8 x 132
#define RED_F   47232      // 256
#define RED2_F  47488      // 256
#define RNR_F   47744      // 128 : r[64], nr[64]
#define GG_F    47872      // 256
#define BB0_F   48128      // 256
#define WOS_F   48384      // 128
#define SCAL_F  48512      // 32 : sq[8] sq2[8] sk[8] sk2[8]
#define PD_F    48544      // 512 : per-warp pair partials [64][8]
#define SMEM_MAIN 196224   // 49056 floats

#define MMA4(base, A, B0, B1) hmma(D + (base), A, B0, B1)

__global__ __launch_bounds__(256, 1)
void main_kernel(const float* __restrict__ Wo, const float* __restrict__ bo,
                 float* __restrict__ out) {
    extern __shared__ char smc[];
    float* smf = (float*)smc;
    const uint32_t sbase = smem_u32(smc);
    const int tid = threadIdx.x;
    const int w = tid >> 5;            // warp 0..7
    const int lane = tid & 31;
    const int s = lane >> 3, i8 = lane & 7;
    const int tg = lane & 3, rowq = lane >> 2;

    // ---- one-time: stage Wc^T hi/lo into smem (row stride 256B, chunk^row&7)
    for (int idx = tid; idx < 4096; idx += 256) {
        const int n = idx >> 4, c = idx & 15;
        const int off = n * 256 + ((c ^ (n & 7)) << 4);
        *(uint4*)(smc + WHI_O + off) = dWcT_hi[idx];
        *(uint4*)(smc + WLO_O + off) = dWcT_lo[idx];
    }
    if (tid < 256) {
        smf[GG_F + tid] = dG[tid];
        smf[BB0_F + tid] = dB0[tid];
        if (tid < 128) smf[WOS_F + tid] = Wo[tid];
    }
    __syncthreads();

    const float bo_v = bo[0];
    const int grid = gridDim.x;

    // ldmatrix lane-address components (constant per thread)
    const uint32_t a_base = sbase + PHI_O + ((((s & 1) << 3) + i8) << 8);
    const uint32_t bu_base = sbase + WHI_O + ((((2 * w + (s >> 1)) << 3) + i8) << 8);
    const uint32_t bv_base = bu_base + 32768;   // +128 n-rows
    const int kb_a = (s >> 1), kb_b = (s & 1);

    for (int t = blockIdx.x; t < NTILES; t += grid) {
        const int b = t >> 12;
        const int i0 = ((t >> 6) & 63) * 8;
        const int j0 = (t & 63) * 8;

        __syncthreads();  // prev tile fully retired (PD consumed, smem free)

        // ---- per-tile operand loads gmem -> smem ----
        {
            const float4* ag = (const float4*)(dAu + (size_t)(b * 512 + i0) * 256);
#pragma unroll
            for (int r = 0; r < 2; r++) {
                int idx = tid + r * 256;
                *(float4*)(smf + AU_F + (idx >> 6) * 260 + (idx & 63) * 4) = ag[idx];
            }
            const float4* bg = (const float4*)(dBk + (size_t)(b * 512 + j0) * 256);
#pragma unroll
            for (int r = 0; r < 2; r++) {
                int idx = tid + r * 256;
                *(float4*)(smf + BK_F + (idx >> 6) * 260 + (idx & 63) * 4) = bg[idx];
            }
            const float4* qg = (const float4*)(d_q + (size_t)(b * 512 + i0) * 128);
            *(float4*)(smf + QS_F + (tid >> 5) * 132 + (tid & 31) * 4) = qg[tid];
            const float4* kg = (const float4*)(d_k + (size_t)(b * 512 + j0) * 128);
            *(float4*)(smf + KS_F + (tid >> 5) * 132 + (tid & 31) * 4) = kg[tid];
            if (tid < 8)       smf[SCAL_F + tid] = dsq [b * 512 + i0 + tid];
            else if (tid < 16) smf[SCAL_F + tid] = dsq2[b * 512 + i0 + tid - 8];
            else if (tid < 24) smf[SCAL_F + tid] = dsk [b * 512 + j0 + tid - 16];
            else if (tid < 32) smf[SCAL_F + tid] = dsk2[b * 512 + j0 + tid - 24];
        }
        __syncthreads();

        // ---- build P hi+lo (bf16, swizzled) + exact fp32 stats partials ----
        {
            const int m = tid & 63, kq = tid >> 6;
            const int iB = m >> 3, jB = m & 7;
            const float* qrow = smf + QS_F + iB * 132;
            const float* krow = smf + KS_F + jB * 132;
            float ss = 0.f, s2 = 0.f;
#pragma unroll
            for (int c8 = 0; c8 < 4; c8++) {
                const int kk = kq * 32 + c8 * 8;
                float4 qa = *(const float4*)(qrow + kk);
                float4 qb = *(const float4*)(qrow + kk + 4);
                float4 ka = *(const float4*)(krow + kk);
                float4 kb = *(const float4*)(krow + kk + 4);
                float p0 = qa.x * ka.x, p1 = qa.y * ka.y;
                float p2 = qa.z * ka.z, p3 = qa.w * ka.w;
                float p4 = qb.x * kb.x, p5 = qb.y * kb.y;
                float p6 = qb.z * kb.z, p7 = qb.w * kb.w;
                ss += ((p0 + p1) + (p2 + p3)) + ((p4 + p5) + (p6 + p7));
                s2 = fmaf(p0, p0, s2); s2 = fmaf(p1, p1, s2);
                s2 = fmaf(p2, p2, s2); s2 = fmaf(p3, p3, s2);
                s2 = fmaf(p4, p4, s2); s2 = fmaf(p5, p5, s2);
                s2 = fmaf(p6, p6, s2); s2 = fmaf(p7, p7, s2);
                __nv_bfloat162 h0 = __floats2bfloat162_rn(p0, p1);
                __nv_bfloat162 h1 = __floats2bfloat162_rn(p2, p3);
                __nv_bfloat162 h2 = __floats2bfloat162_rn(p4, p5);
                __nv_bfloat162 h3 = __floats2bfloat162_rn(p6, p7);
                __nv_bfloat162 l0 = __floats2bfloat162_rn(p0 - __low2float(h0), p1 - __high2float(h0));
                __nv_bfloat162 l1 = __floats2bfloat162_rn(p2 - __low2float(h1), p3 - __high2float(h1));
                __nv_bfloat162 l2 = __floats2bfloat162_rn(p4 - __low2float(h2), p5 - __high2float(h2));
                __nv_bfloat162 l3 = __floats2bfloat162_rn(p6 - __low2float(h3), p7 - __high2float(h3));
                uint4 sh, sl;
                sh.x = *(uint32_t*)&h0; sh.y = *(uint32_t*)&h1;
                sh.z = *(uint32_t*)&h2; sh.w = *(uint32_t*)&h3;
                sl.x = *(uint32_t*)&l0; sl.y = *(uint32_t*)&l1;
                sl.z = *(uint32_t*)&l2; sl.w = *(uint32_t*)&l3;
                const int off = m * 256 + (((kk >> 3) ^ (m & 7)) << 4);
                *(uint4*)(smc + PHI_O + off) = sh;
                *(uint4*)(smc + PLO_O + off) = sl;
            }
            smf[RED_F + kq * 64 + m] = ss;
            smf[RED2_F + kq * 64 + m] = s2;
        }
        __syncthreads();

        // ---- LN stats (tid<64) then everyone runs the MMA loop ----
        if (tid < 64) {
            float ss = smf[RED_F + tid] + smf[RED_F + 64 + tid] +
                       smf[RED_F + 128 + tid] + smf[RED_F + 192 + tid];
            float s2 = smf[RED2_F + tid] + smf[RED2_F + 64 + tid] +
                       smf[RED2_F + 128 + tid] + smf[RED2_F + 192 + tid];
            const int i2 = tid >> 3, j2 = tid & 7;
            float mu = (smf[SCAL_F + i2] + smf[SCAL_F + 16 + j2] + ss) * (1.f / 384.f);
            float e2 = (smf[SCAL_F + 8 + i2] + smf[SCAL_F + 24 + j2] + s2) * (1.f / 384.f);
            float r = rsqrtf(e2 - mu * mu + EPSV);
            smf[RNR_F + tid] = r;
            smf[RNR_F + 64 + tid] = -r * mu;
        }

        // ---- cross GEMM: 3-pass bf16x3 via mma.sync ----
        float D[64];
#pragma unroll
        for (int x = 0; x < 64; x++) D[x] = 0.f;

#pragma unroll 2
        for (int kf = 0; kf < 8; kf++) {
            uint32_t bu[4], blu[4], bv[4], blv[4];
            const uint32_t cb = (uint32_t)(((2 * kf + kb_b) ^ i8) << 4);
            ldsm4(bu,  bu_base + cb);
            ldsm4(blu, bu_base + 65536 + cb);
            ldsm4(bv,  bv_base + cb);
            ldsm4(blv, bv_base + 65536 + cb);
            const uint32_t ca = (uint32_t)(((2 * kf + kb_a) ^ i8) << 4);
#pragma unroll
            for (int mf = 0; mf < 4; mf++) {
                uint32_t ah[4], al[4];
                const uint32_t aaddr = a_base + mf * 4096 + ca;
                ldsm4(ah, aaddr);
                ldsm4(al, aaddr + 16384);
                const int base = mf * 16;
                MMA4(base + 0,  ah, bu[0],  bu[1]);
                MMA4(base + 0,  al, bu[0],  bu[1]);
                MMA4(base + 0,  ah, blu[0], blu[1]);
                MMA4(base + 4,  ah, bu[2],  bu[3]);
                MMA4(base + 4,  al, bu[2],  bu[3]);
                MMA4(base + 4,  ah, blu[2], blu[3]);
                MMA4(base + 8,  ah, bv[0],  bv[1]);
                MMA4(base + 8,  al, bv[0],  bv[1]);
                MMA4(base + 8,  ah, blv[0], blv[1]);
                MMA4(base + 12, ah, bv[2],  bv[3]);
                MMA4(base + 12, al, bv[2],  bv[3]);
                MMA4(base + 12, ah, blv[2], blv[3]);
            }
        }
        __syncthreads();  // D complete everywhere; RNR ready

        // ---- fused epilogue on register accumulators ----
#pragma unroll
        for (int mf = 0; mf < 4; mf++) {
#pragma unroll
            for (int half = 0; half < 2; half++) {
                const int p = mf * 16 + half * 8 + rowq;
                const float rr = smf[RNR_F + p];
                const float nr = smf[RNR_F + 64 + p];
                const int ip = p >> 3, jp = p & 7;
                float z = 0.f;
#pragma unroll
                for (int nf = 0; nf < 2; nf++) {
#pragma unroll
                    for (int e = 0; e < 2; e++) {
                        const int h = w * 16 + nf * 8 + tg * 2 + e;
                        const float Cu = D[mf * 16 + nf * 4 + half * 2 + e];
                        const float Cv = D[mf * 16 + (2 + nf) * 4 + half * 2 + e];
                        float u = fmaf(rr, smf[AU_F + ip * 260 + h] +
                                           smf[BK_F + jp * 260 + h] + Cu,
                                       fmaf(nr, smf[GG_F + h], smf[BB0_F + h]));
                        float v = fmaf(rr, smf[AU_F + ip * 260 + 128 + h] +
                                           smf[BK_F + jp * 260 + 128 + h] + Cv,
                                       fmaf(nr, smf[GG_F + 128 + h], smf[BB0_F + 128 + h]));
                        z = fmaf(u * gelu_ex(v), smf[WOS_F + h], z);
                    }
                }
                z += __shfl_xor_sync(0xffffffffu, z, 1);
                z += __shfl_xor_sync(0xffffffffu, z, 2);
                if (tg == 0) smf[PD_F + p * 8 + w] = z;
            }
        }
        __syncthreads();

        // ---- combine 8 warp partials, store ----
        if (tid < 64) {
            float acc = bo_v;
#pragma unroll
            for (int ww = 0; ww < 8; ww++) acc += smf[PD_F + tid * 8 + ww];
            out[(size_t)(b * 512 + i0 + (tid >> 3)) * 512 + j0 + (tid & 7)] = acc;
        }
    }
}

// ===========================================================================
// launcher
// ===========================================================================
extern "C" void kernel_launch(void* const* d_in, const int* in_sizes, int n_in,
                              void* d_out, int out_size) {
    const float* Q    = (const float*)d_in[0];
    const float* K    = (const float*)d_in[1];
    const float* Wq   = (const float*)d_in[2];
    const float* Wk   = (const float*)d_in[3];
    const float* ln_g = (const float*)d_in[4];
    const float* ln_b = (const float*)d_in[5];
    const float* Wu   = (const float*)d_in[6];
    const float* bu   = (const float*)d_in[7];
    const float* Wv   = (const float*)d_in[8];
    const float* bv   = (const float*)d_in[9];
    const float* Wo   = (const float*)d_in[10];
    const float* bo   = (const float*)d_in[11];
    float* out = (float*)d_out;

    int nsm = 148;
    cudaDeviceGetAttribute(&nsm, cudaDevAttrMultiProcessorCount, 0);

    cudaFuncSetAttribute(main_kernel, cudaFuncAttributeMaxDynamicSharedMemorySize, SMEM_MAIN);

    deriv_kernel<<<256, 384>>>(ln_g, ln_b, Wu, bu, Wv, bv);
    proj_kernel<<<256, 128>>>(Q, K, Wq, Wk);
    main_kernel<<<nsm, 256, SMEM_MAIN>>>(Wo, bo, out);
}